// round 9
// baseline (speedup 1.0000x reference)
#include <cuda_runtime.h>
#include <math.h>

// B=32, C=32, H=64, W=64, pool 2x2 -> 32x32 pooled positions per channel.
// Block (256 thr, 8 warps) owns one (c, h2) slab; lane = pooled w2.
// Warp q accumulates the 9 linear batch-sums over i in [4q, 4q+4).
// Two passes (a-tensors, then b-tensors) keep registers low; no barriers in
// the hot loops. One smem merge + nonlinear combine at the end.
//
// Scaling trick: with s = sum of 4 exp() values, pooled var v = s/16, so
// 1/v^2 = 256/s^2 (factor 256 applied once in the combine), and
// log-term difference la-lb = log(sb) - log(sa) (all constants cancel,
// +1e-6 dropped: ~1e-6 relative, far below the 1e-3 tolerance).

__device__ double g_part[1024];
__device__ unsigned int g_count = 0;   // self-resetting

__global__ __launch_bounds__(256, 6) void k_main(
    const float* __restrict__ mu_a, const float* __restrict__ lv_a,
    const float* __restrict__ mu_b, const float* __restrict__ lv_b,
    float* __restrict__ out)
{
    __shared__ float s_p[8][32][9];    // [warp][lane=w2][sum]
    __shared__ bool  s_last;

    const int t    = threadIdx.x;
    const int lane = t & 31;           // w2
    const int wq   = t >> 5;           // batch chunk 0..7 (4 i's each)
    const int b    = blockIdx.x;
    const int c    = b >> 5;
    const int h2   = b & 31;

    const int istride = 32 * 64 * 64;  // batch stride (floats)
    const int base0 = (4 * wq) * istride + (c * 64 + 2 * h2) * 64 + 2 * lane;

    // ---- Pass A: mu_a / lv_a ----
    float S1 = 0.f, SS = 0.f, La = 0.f;          // SS = S2 + S3 (S3 via s^2/256)
    float U0a = 0.f, U1a = 0.f, U2a = 0.f;       // unscaled: sum r^2, ma r^2, ma^2 r^2
    {
        int ofs = base0;
        #pragma unroll 2
        for (int i = 0; i < 4; i++) {
            float2 A0  = *(const float2*)(mu_a + ofs);
            float2 A1  = *(const float2*)(mu_a + ofs + 64);
            float2 La0 = *(const float2*)(lv_a + ofs);
            float2 La1 = *(const float2*)(lv_a + ofs + 64);
            ofs += istride;

            float ma = (A0.x + A0.y + A1.x + A1.y) * 0.25f;
            float sa = __expf(La0.x) + __expf(La0.y) + __expf(La1.x) + __expf(La1.y);
            float ma2 = ma * ma;
            float r   = __frcp_rn(sa);           // 1/sa (independent of log chain)
            float r2  = r * r;                   // 1/va^2 = 256*r2 (scaled later)
            S1 += ma;
            SS += fmaf(sa * sa, 0.00390625f, ma2);   // ma^2 + (sa/16)^2
            U0a += r2; U1a += ma * r2; U2a += ma2 * r2;
            La  += __logf(sa);
        }
    }

    // ---- Pass B: mu_b / lv_b ----
    float U0b = 0.f, U1b = 0.f, U2b = 0.f, Lb = 0.f;
    {
        int ofs = base0;
        #pragma unroll 2
        for (int i = 0; i < 4; i++) {
            float2 B0  = *(const float2*)(mu_b + ofs);
            float2 B1  = *(const float2*)(mu_b + ofs + 64);
            float2 Lb0 = *(const float2*)(lv_b + ofs);
            float2 Lb1 = *(const float2*)(lv_b + ofs + 64);
            ofs += istride;

            float mb = (B0.x + B0.y + B1.x + B1.y) * 0.25f;
            float sb = __expf(Lb0.x) + __expf(Lb0.y) + __expf(Lb1.x) + __expf(Lb1.y);
            float mb2 = mb * mb;
            float r   = __frcp_rn(sb);
            float r2  = r * r;
            U0b += r2; U1b += mb * r2; U2b += mb2 * r2;
            Lb  += __logf(sb);
        }
    }

    // publish partial sums (L contribution: la - lb = log(sb) - log(sa))
    s_p[wq][lane][0] = S1;  s_p[wq][lane][1] = SS;
    s_p[wq][lane][2] = U0a; s_p[wq][lane][3] = U1a; s_p[wq][lane][4] = U2a;
    s_p[wq][lane][5] = U0b; s_p[wq][lane][6] = U1b; s_p[wq][lane][7] = U2b;
    s_p[wq][lane][8] = Lb - La;
    __syncthreads();

    if (wq == 0) {
        float m[9];
        #pragma unroll
        for (int k = 0; k < 9; k++) {
            float acc = 0.f;
            #pragma unroll
            for (int w = 0; w < 8; w++) acc += s_p[w][lane][k];
            m[k] = acc;
        }

        // sum_ij diff = 32*L - 256*[0.5*SS*U0a - S1*U1a + 16*U2a]
        //                    + 256*[0.5*SS*U0b - S1*U1b + 16*U2b]
        float pa = 0.5f * m[1] * m[2] - m[0] * m[3] + 16.0f * m[4];
        float pb = 0.5f * m[1] * m[5] - m[0] * m[6] + 16.0f * m[7];
        double contrib = 32.0 * (double)m[8] + 256.0 * ((double)pb - (double)pa);

        #pragma unroll
        for (int o = 16; o; o >>= 1)
            contrib += __shfl_xor_sync(0xffffffffu, contrib, o);

        if (lane == 0) {
            g_part[b] = contrib;
            __threadfence();
            unsigned int prev = atomicInc(&g_count, 0xffffffffu);
            s_last = (prev == gridDim.x - 1);
        }
    }
    __syncthreads();

    if (s_last) {
        // 256 threads reduce 1024 partials: 4 each, then tree.
        double v = 0.0;
        #pragma unroll
        for (int k = 0; k < 4; k++) v += g_part[t + 256 * k];
        #pragma unroll
        for (int o = 16; o; o >>= 1)
            v += __shfl_xor_sync(0xffffffffu, v, o);
        __shared__ double s_f[8];
        if ((t & 31) == 0) s_f[t >> 5] = v;
        __syncthreads();
        if (t == 0) {
            double s = 0.0;
            #pragma unroll
            for (int w = 0; w < 8; w++) s += s_f[w];
            out[0] = (float)(s * (1.0 / 1024.0));   // /(B*B)
            g_count = 0;   // reset for next graph replay
        }
    }
}

extern "C" void kernel_launch(void* const* d_in, const int* in_sizes, int n_in,
                              void* d_out, int out_size) {
    const float* mu_a = (const float*)d_in[0];
    const float* lv_a = (const float*)d_in[1];
    const float* mu_b = (const float*)d_in[2];
    const float* lv_b = (const float*)d_in[3];

    k_main<<<1024, 256>>>(mu_a, lv_a, mu_b, lv_b, (float*)d_out);
}

// round 10
// speedup vs baseline: 1.1658x; 1.1658x over previous
#include <cuda_runtime.h>
#include <math.h>

// B=32, C=32, H=64, W=64, pool 2x2 -> 32x32 pooled positions per channel.
// Block (128 thr, 4 warps) owns one (c, h2) slab; lane = pooled w2.
// Warp q accumulates 9 linear batch-sums over i in [8q, 8q+8); two passes
// (a-tensors then b-tensors); no barriers in the hot loops.
//
// exp() is computed on the FMA/ALU pipes (polynomial), NOT MUFU — the 33.5M
// exponentials were saturating the SFU pipe and capping DRAM at ~50%.

__device__ double g_part[1024];
__device__ unsigned int g_count = 0;   // self-resetting

// exp(x) for |x| <~ 30: t = x*log2e; 2^round(t) * poly(frac). ~4e-5 rel err.
// All fma/alu pipe: no MUFU.
__device__ __forceinline__ float fexp(float x) {
    float t  = x * 1.4426950408889634f;
    float fr = t + 12582912.0f;               // round-to-nearest via 1.5*2^23
    int   n  = __float_as_int(fr) - 0x4B400000;
    float f  = t - (fr - 12582912.0f);        // frac in [-0.5, 0.5]
    float p  = 0.009618130f;                  // 2^f Taylor deg-4
    p = fmaf(p, f, 0.055504109f);
    p = fmaf(p, f, 0.240226507f);
    p = fmaf(p, f, 0.693147181f);
    p = fmaf(p, f, 1.0f);
    return __int_as_float(__float_as_int(p) + (n << 23));
}

__global__ __launch_bounds__(128, 8) void k_main(
    const float* __restrict__ mu_a, const float* __restrict__ lv_a,
    const float* __restrict__ mu_b, const float* __restrict__ lv_b,
    float* __restrict__ out)
{
    __shared__ float s_p[4][32][9];    // [warp][lane=w2][sum]
    __shared__ bool  s_last;

    const int t    = threadIdx.x;
    const int lane = t & 31;           // w2
    const int wq   = t >> 5;           // batch chunk 0..3 (8 i's each)
    const int b    = blockIdx.x;
    const int c    = b >> 5;
    const int h2   = b & 31;

    const int istride = 32 * 64 * 64;  // batch stride (floats)
    const int base0 = (8 * wq) * istride + (c * 64 + 2 * h2) * 64 + 2 * lane;

    // ---- Pass A: mu_a / lv_a ----
    float S1 = 0.f, SS = 0.f, La = 0.f;      // SS = sum(ma^2 + (sa/16)^2)
    float U0a = 0.f, U1a = 0.f, U2a = 0.f;   // unscaled by 256 (applied in combine)
    {
        int ofs = base0;
        #pragma unroll 2
        for (int i = 0; i < 8; i++) {
            float2 A0  = *(const float2*)(mu_a + ofs);
            float2 A1  = *(const float2*)(mu_a + ofs + 64);
            float2 La0 = *(const float2*)(lv_a + ofs);
            float2 La1 = *(const float2*)(lv_a + ofs + 64);
            ofs += istride;

            float ma = (A0.x + A0.y + A1.x + A1.y) * 0.25f;
            float sa = fexp(La0.x) + fexp(La0.y) + fexp(La1.x) + fexp(La1.y);
            float ma2 = ma * ma;
            float r   = __frcp_rn(sa);
            float r2  = r * r;                       // 1/va^2 = 256*r2
            S1 += ma;
            SS += fmaf(sa * sa, 0.00390625f, ma2);   // ma^2 + (sa/16)^2
            U0a += r2; U1a += ma * r2; U2a += ma2 * r2;
            La  += __logf(sa);
        }
    }

    // ---- Pass B: mu_b / lv_b ----
    float U0b = 0.f, U1b = 0.f, U2b = 0.f, Lb = 0.f;
    {
        int ofs = base0;
        #pragma unroll 2
        for (int i = 0; i < 8; i++) {
            float2 B0  = *(const float2*)(mu_b + ofs);
            float2 B1  = *(const float2*)(mu_b + ofs + 64);
            float2 Lb0 = *(const float2*)(lv_b + ofs);
            float2 Lb1 = *(const float2*)(lv_b + ofs + 64);
            ofs += istride;

            float mb = (B0.x + B0.y + B1.x + B1.y) * 0.25f;
            float sb = fexp(Lb0.x) + fexp(Lb0.y) + fexp(Lb1.x) + fexp(Lb1.y);
            float mb2 = mb * mb;
            float r   = __frcp_rn(sb);
            float r2  = r * r;
            U0b += r2; U1b += mb * r2; U2b += mb2 * r2;
            Lb  += __logf(sb);
        }
    }

    // publish partials (la - lb = log(sb) - log(sa): constants cancel)
    s_p[wq][lane][0] = S1;  s_p[wq][lane][1] = SS;
    s_p[wq][lane][2] = U0a; s_p[wq][lane][3] = U1a; s_p[wq][lane][4] = U2a;
    s_p[wq][lane][5] = U0b; s_p[wq][lane][6] = U1b; s_p[wq][lane][7] = U2b;
    s_p[wq][lane][8] = Lb - La;
    __syncthreads();

    if (wq == 0) {
        float m[9];
        #pragma unroll
        for (int k = 0; k < 9; k++)
            m[k] = s_p[0][lane][k] + s_p[1][lane][k] + s_p[2][lane][k] + s_p[3][lane][k];

        // sum_ij diff = 32*L - 256*[0.5*SS*U0a - S1*U1a + 16*U2a]
        //                    + 256*[0.5*SS*U0b - S1*U1b + 16*U2b]
        float pa = 0.5f * m[1] * m[2] - m[0] * m[3] + 16.0f * m[4];
        float pb = 0.5f * m[1] * m[5] - m[0] * m[6] + 16.0f * m[7];
        double contrib = 32.0 * (double)m[8] + 256.0 * ((double)pb - (double)pa);

        #pragma unroll
        for (int o = 16; o; o >>= 1)
            contrib += __shfl_xor_sync(0xffffffffu, contrib, o);

        if (lane == 0) {
            g_part[b] = contrib;
            __threadfence();
            unsigned int prev = atomicInc(&g_count, 0xffffffffu);
            s_last = (prev == gridDim.x - 1);
        }
    }
    __syncthreads();

    if (s_last) {
        double v = 0.0;
        #pragma unroll
        for (int k = 0; k < 8; k++) v += g_part[t + 128 * k];
        #pragma unroll
        for (int o = 16; o; o >>= 1)
            v += __shfl_xor_sync(0xffffffffu, v, o);
        __shared__ double s_f[4];
        if ((t & 31) == 0) s_f[t >> 5] = v;
        __syncthreads();
        if (t == 0) {
            out[0] = (float)((s_f[0] + s_f[1] + s_f[2] + s_f[3]) * (1.0 / 1024.0)); // /(B*B)
            g_count = 0;   // reset for next graph replay
        }
    }
}

extern "C" void kernel_launch(void* const* d_in, const int* in_sizes, int n_in,
                              void* d_out, int out_size) {
    const float* mu_a = (const float*)d_in[0];
    const float* lv_a = (const float*)d_in[1];
    const float* mu_b = (const float*)d_in[2];
    const float* lv_b = (const float*)d_in[3];

    k_main<<<1024, 128>>>(mu_a, lv_a, mu_b, lv_b, (float*)d_out);
}

// round 11
// speedup vs baseline: 1.2234x; 1.0494x over previous
#include <cuda_runtime.h>
#include <math.h>

// B=32, C=32, H=64, W=64, pool 2x2 -> 32x32 pooled positions per channel.
// Block (128 thr, 4 warps) owns one (c, h2) slab; lane = pooled w2.
// Warp q accumulates 9 linear batch-sums over i in [8q, 8q+8) in ONE pass
// (all 4 tensors per iteration -> max loads in flight); no barriers in the
// hot loop. Smem merge + nonlinear combine once per block, then a single
// double atomicAdd; last block writes the scalar out.
//
// exp work is split between MUFU (__expf) and the FMA pipe (poly) so neither
// pipe throttles the DRAM stream. Algebra: raw exp-sums s (v = s/16), so
// 1/v^2 = 256/s^2 (256 hoisted to the combine) and la-lb = log(sb)-log(sa).

__device__ double g_acc = 0.0;
__device__ unsigned int g_count = 0;   // self-resetting

// exp(x) on the FMA/ALU pipes, ~4e-5 rel err for |x| < 30.
__device__ __forceinline__ float fexp(float x) {
    float t  = x * 1.4426950408889634f;
    float fr = t + 12582912.0f;               // round via 1.5*2^23
    int   n  = __float_as_int(fr) - 0x4B400000;
    float f  = t - (fr - 12582912.0f);        // frac in [-0.5, 0.5]
    float p  = 0.009618130f;
    p = fmaf(p, f, 0.055504109f);
    p = fmaf(p, f, 0.240226507f);
    p = fmaf(p, f, 0.693147181f);
    p = fmaf(p, f, 1.0f);
    return __int_as_float(__float_as_int(p) + (n << 23));
}

__global__ __launch_bounds__(128, 8) void k_main(
    const float* __restrict__ mu_a, const float* __restrict__ lv_a,
    const float* __restrict__ mu_b, const float* __restrict__ lv_b,
    float* __restrict__ out)
{
    __shared__ float s_p[4][32][9];    // [warp][lane=w2][sum]
    __shared__ bool  s_last;

    const int t    = threadIdx.x;
    const int lane = t & 31;           // w2
    const int wq   = t >> 5;           // batch chunk 0..3 (8 i's each)
    const int b    = blockIdx.x;
    const int c    = b >> 5;
    const int h2   = b & 31;

    const int istride = 32 * 64 * 64;  // batch stride (floats)
    int ofs = (8 * wq) * istride + (c * 64 + 2 * h2) * 64 + 2 * lane;

    float S1 = 0.f, SS = 0.f, Ld = 0.f;          // SS = sum(ma^2 + (sa/16)^2)
    float U0a = 0.f, U1a = 0.f, U2a = 0.f;       // unscaled (x256 in combine)
    float U0b = 0.f, U1b = 0.f, U2b = 0.f;

    #pragma unroll 2
    for (int i = 0; i < 8; i++) {
        float2 A0  = *(const float2*)(mu_a + ofs);
        float2 A1  = *(const float2*)(mu_a + ofs + 64);
        float2 La0 = *(const float2*)(lv_a + ofs);
        float2 La1 = *(const float2*)(lv_a + ofs + 64);
        float2 B0  = *(const float2*)(mu_b + ofs);
        float2 B1  = *(const float2*)(mu_b + ofs + 64);
        float2 Lb0 = *(const float2*)(lv_b + ofs);
        float2 Lb1 = *(const float2*)(lv_b + ofs + 64);
        ofs += istride;

        float ma = (A0.x + A0.y + A1.x + A1.y) * 0.25f;
        float mb = (B0.x + B0.y + B1.x + B1.y) * 0.25f;
        // 2 exps on MUFU + 2 on FMA pipe per quad
        float sa = (__expf(La0.x) + fexp(La0.y)) + (__expf(La1.x) + fexp(La1.y));
        float sb = (__expf(Lb0.x) + fexp(Lb0.y)) + (__expf(Lb1.x) + fexp(Lb1.y));

        float ma2 = ma * ma, mb2 = mb * mb;
        float ra = __frcp_rn(sa); float ra2 = ra * ra;
        float rb = __frcp_rn(sb); float rb2 = rb * rb;

        S1 += ma;
        SS += fmaf(sa * sa, 0.00390625f, ma2);   // ma^2 + (sa/16)^2
        U0a += ra2; U1a += ma * ra2; U2a += ma2 * ra2;
        U0b += rb2; U1b += mb * rb2; U2b += mb2 * rb2;
        Ld  += __logf(sb) - __logf(sa);          // la - lb (constants cancel)
    }

    s_p[wq][lane][0] = S1;  s_p[wq][lane][1] = SS;
    s_p[wq][lane][2] = U0a; s_p[wq][lane][3] = U1a; s_p[wq][lane][4] = U2a;
    s_p[wq][lane][5] = U0b; s_p[wq][lane][6] = U1b; s_p[wq][lane][7] = U2b;
    s_p[wq][lane][8] = Ld;
    __syncthreads();

    if (wq == 0) {
        float m[9];
        #pragma unroll
        for (int k = 0; k < 9; k++)
            m[k] = s_p[0][lane][k] + s_p[1][lane][k] + s_p[2][lane][k] + s_p[3][lane][k];

        // sum_ij diff = 32*L - 256*[0.5*SS*U0a - S1*U1a + 16*U2a]
        //                    + 256*[0.5*SS*U0b - S1*U1b + 16*U2b]
        float pa = 0.5f * m[1] * m[2] - m[0] * m[3] + 16.0f * m[4];
        float pb = 0.5f * m[1] * m[5] - m[0] * m[6] + 16.0f * m[7];
        double contrib = 32.0 * (double)m[8] + 256.0 * ((double)pb - (double)pa);

        #pragma unroll
        for (int o = 16; o; o >>= 1)
            contrib += __shfl_xor_sync(0xffffffffu, contrib, o);

        if (lane == 0) {
            atomicAdd(&g_acc, contrib);
            __threadfence();
            unsigned int prev = atomicInc(&g_count, 0xffffffffu);
            s_last = (prev == gridDim.x - 1);
        }
    }
    __syncthreads();

    if (s_last && t == 0) {
        out[0] = (float)(g_acc * (1.0 / 1024.0));   // /(B*B)
        g_acc = 0.0;                                // reset for next replay
        g_count = 0;
    }
}

extern "C" void kernel_launch(void* const* d_in, const int* in_sizes, int n_in,
                              void* d_out, int out_size) {
    const float* mu_a = (const float*)d_in[0];
    const float* lv_a = (const float*)d_in[1];
    const float* mu_b = (const float*)d_in[2];
    const float* lv_b = (const float*)d_in[3];

    k_main<<<1024, 128>>>(mu_a, lv_a, mu_b, lv_b, (float*)d_out);
}